// round 8
// baseline (speedup 1.0000x reference)
#include <cuda_runtime.h>
#include <cuda_fp16.h>
#include <math.h>

#define N_NODES 50000
#define N_EDGES 800000
#define ET (N_EDGES + N_NODES)   // edges + self loops = 850000
#define F_IN 128
#define H 256
#define G_GRAPHS 500
#define FC1 196
#define D_OUT 10
#define NEG 0.2f
#define NB_SCAN ((N_NODES + 1023) / 1024)   // 49 scan blocks

// ---------------- scratch (static device globals; no allocation) ----------------
__device__ float g_featB[(size_t)N_NODES * H];   // aggregated output / next-layer input
__device__ __align__(16) __half g_featH[(size_t)N_NODES * H]; // fp16 h for gather
__device__ float g_as[N_NODES];                  // x . (W a_s) per node
__device__ float g_ad[N_NODES];                  // x . (W a_d) per node
__device__ float g_wvs[3][H];                    // W @ a_s per layer
__device__ float g_wvd[3][H];                    // W @ a_d per layer
__device__ float g_e[ET];                        // per-edge exp(e - m) (slow path)
__device__ int   g_deg[N_NODES];
__device__ int   g_off[N_NODES + 1];             // CSR row offsets (by dst)
__device__ int   g_pos[N_NODES];
__device__ int   g_srcs[ET];                     // CSR column indices (src node)
__device__ int   g_bsum[NB_SCAN];
__device__ int   g_bpre[NB_SCAN];
__device__ float g_hg[G_GRAPHS * H];             // pooled per-graph sums
__device__ float g_cnt[G_GRAPHS];
__device__ float g_fc1[G_GRAPHS * FC1];

// ================= CSR build =================
__global__ void zero_deg() {
    int i = blockIdx.x * blockDim.x + threadIdx.x;
    if (i < N_NODES) g_deg[i] = 0;
    if (i < G_GRAPHS * H) g_hg[i] = 0.f;
    if (i < G_GRAPHS) g_cnt[i] = 0.f;
}

// merged: in-degree histogram + per-graph node counts
__global__ void count_all(const int* __restrict__ ei, const int* __restrict__ batch) {
    int e = blockIdx.x * blockDim.x + threadIdx.x;
    if (e < ET) {
        int d = (e < N_EDGES) ? ei[N_EDGES + e] : (e - N_EDGES);
        atomicAdd(&g_deg[d], 1);
    }
    if (e < N_NODES) atomicAdd(&g_cnt[batch[e]], 1.f);
}

__global__ __launch_bounds__(1024) void scan_local() {
    __shared__ int ws[32];
    int tid = threadIdx.x, lane = tid & 31, wid = tid >> 5;
    int i = blockIdx.x * 1024 + tid;
    int v = (i < N_NODES) ? g_deg[i] : 0;
    int incl = v;
#pragma unroll
    for (int o = 1; o < 32; o <<= 1) {
        int t = __shfl_up_sync(0xFFFFFFFFu, incl, o);
        if (lane >= o) incl += t;
    }
    if (lane == 31) ws[wid] = incl;
    __syncthreads();
    if (wid == 0) {
        int w = ws[lane];
#pragma unroll
        for (int o = 1; o < 32; o <<= 1) {
            int t = __shfl_up_sync(0xFFFFFFFFu, w, o);
            if (lane >= o) w += t;
        }
        ws[lane] = w;
    }
    __syncthreads();
    int excl = (wid ? ws[wid - 1] : 0) + incl - v;
    if (i < N_NODES) g_off[i] = excl;
    if (tid == 0) g_bsum[blockIdx.x] = ws[31];
}

__global__ void scan_bsums() {
    __shared__ int sh[64];
    int tid = threadIdx.x;
    int v = (tid < NB_SCAN) ? g_bsum[tid] : 0;
    sh[tid] = v;
    __syncthreads();
#pragma unroll
    for (int o = 1; o < 64; o <<= 1) {
        int t = (tid >= o) ? sh[tid - o] : 0;
        __syncthreads();
        sh[tid] += t;
        __syncthreads();
    }
    if (tid < NB_SCAN) g_bpre[tid] = sh[tid] - v;
}

__global__ void scan_add() {
    int i = blockIdx.x * blockDim.x + threadIdx.x;
    if (i == 0) g_off[N_NODES] = ET;
    if (i < N_NODES) {
        int o = g_off[i] + g_bpre[i >> 10];
        g_off[i] = o;
        g_pos[i] = o;
    }
}

__global__ void scatter_edges(const int* __restrict__ ei) {
    int e = blockIdx.x * blockDim.x + threadIdx.x;
    if (e >= ET) return;
    int s, d;
    if (e < N_EDGES) { s = ei[e]; d = ei[N_EDGES + e]; }
    else             { s = d = e - N_EDGES; }
    int idx = atomicAdd(&g_pos[d], 1);
    g_srcs[idx] = s;
}

// ================= wv for ALL layers upfront (warp per output k) =================
__global__ void wv_all(const float* __restrict__ W1, const float* __restrict__ a1s, const float* __restrict__ a1d,
                       const float* __restrict__ W2, const float* __restrict__ a2s, const float* __restrict__ a2d,
                       const float* __restrict__ W3, const float* __restrict__ a3s, const float* __restrict__ a3d) {
    int w = (blockIdx.x * blockDim.x + threadIdx.x) >> 5;   // 0..639
    int lane = threadIdx.x & 31;
    if (w >= F_IN + 2 * H) return;
    int l, k;
    const float *W, *as_, *ad_;
    if (w < F_IN)          { l = 0; k = w;           W = W1; as_ = a1s; ad_ = a1d; }
    else if (w < F_IN + H) { l = 1; k = w - F_IN;    W = W2; as_ = a2s; ad_ = a2d; }
    else                   { l = 2; k = w - F_IN - H; W = W3; as_ = a3s; ad_ = a3d; }
    const float4* wr = (const float4*)(W + (size_t)k * H);
    const float4* sa = (const float4*)as_;
    const float4* da = (const float4*)ad_;
    float4 w0 = wr[lane], w1 = wr[lane + 32];
    float4 s0 = sa[lane], s1 = sa[lane + 32];
    float4 d0 = da[lane], d1 = da[lane + 32];
    float s = w0.x * s0.x + w0.y * s0.y + w0.z * s0.z + w0.w * s0.w
            + w1.x * s1.x + w1.y * s1.y + w1.z * s1.z + w1.w * s1.w;
    float d = w0.x * d0.x + w0.y * d0.y + w0.z * d0.z + w0.w * d0.w
            + w1.x * d1.x + w1.y * d1.y + w1.z * d1.z + w1.w * d1.w;
#pragma unroll
    for (int o = 16; o; o >>= 1) {
        s += __shfl_down_sync(0xFFFFFFFFu, s, o);
        d += __shfl_down_sync(0xFFFFFFFFu, d, o);
    }
    if (lane == 0) { g_wvs[l][k] = s; g_wvd[l][k] = d; }
}

// ================= fp16 TC GEMM (m16n8k16, ldmatrix, double-buffered) =================
// featH(fp16)[M,256] = A[M,K] @ W[K,256]; g_as/g_ad = A @ wv (fp32 exact, in loader).
__device__ __forceinline__ unsigned pkh2(float a, float b) {
    __half2 h = __floats2half2_rn(a, b);
    return *(unsigned*)&h;
}

#define AS_STRIDE 40    // halves per A row (32 + 8 pad)
#define BS_STRIDE 136   // halves per B k-row (128 + 8 pad)

__global__ __launch_bounds__(256) void sgemm_tc(const float* __restrict__ A,
                                                const float* __restrict__ W,
                                                int M, int K, int layer) {
    __shared__ __half As[2][128 * AS_STRIDE];
    __shared__ __half Bs[2][32 * BS_STRIDE];

    int tid = threadIdx.x;
    int wid = tid >> 5, lane = tid & 31;
    int grp = lane >> 2, t4 = lane & 3;
    int wm = wid >> 2, wn = wid & 3;           // warp grid 2x4, warp tile 64x32
    int row0 = blockIdx.y * 128;
    int col0 = blockIdx.x * 128;

    int arow = tid >> 1;                       // 0..127
    int akoff = (tid & 1) * 16;                // 0 or 16
    int brow = tid >> 3;                       // 0..31
    int bnoff = (tid & 7) * 16;                // 0..112

    const float* wvs = g_wvs[layer];
    const float* wvd = g_wvd[layer];

    float acc[4][4][4] = {};
    float ds = 0.f, dd = 0.f;                  // attn-dot partials (row arow)
    float4 ar[4], br[4];
    int gr_a = row0 + arow;

    int nit = K >> 5;

    // ---- LDG stage (tile it) ----
    auto ldg = [&](int it) {
        int k0 = it * 32;
#pragma unroll
        for (int c = 0; c < 4; c++) {
            ar[c] = (gr_a < M) ? *(const float4*)(A + (size_t)gr_a * K + k0 + akoff + c * 4)
                               : make_float4(0.f, 0.f, 0.f, 0.f);
            br[c] = *(const float4*)(W + (size_t)(k0 + brow) * 256 + col0 + bnoff + c * 4);
            float4 wv = *(const float4*)(wvs + k0 + akoff + c * 4);
            float4 wd = *(const float4*)(wvd + k0 + akoff + c * 4);
            ds += ar[c].x * wv.x + ar[c].y * wv.y + ar[c].z * wv.z + ar[c].w * wv.w;
            dd += ar[c].x * wd.x + ar[c].y * wd.y + ar[c].z * wd.z + ar[c].w * wd.w;
        }
    };
    // ---- SMEM store stage ----
    auto sts = [&](int buf) {
        __half* ap = &As[buf][arow * AS_STRIDE + akoff];
        uint4 u0 = make_uint4(pkh2(ar[0].x, ar[0].y), pkh2(ar[0].z, ar[0].w),
                              pkh2(ar[1].x, ar[1].y), pkh2(ar[1].z, ar[1].w));
        uint4 u1 = make_uint4(pkh2(ar[2].x, ar[2].y), pkh2(ar[2].z, ar[2].w),
                              pkh2(ar[3].x, ar[3].y), pkh2(ar[3].z, ar[3].w));
        *(uint4*)ap = u0;
        *(uint4*)(ap + 8) = u1;
        __half* bp = &Bs[buf][brow * BS_STRIDE + bnoff];
        uint4 v0 = make_uint4(pkh2(br[0].x, br[0].y), pkh2(br[0].z, br[0].w),
                              pkh2(br[1].x, br[1].y), pkh2(br[1].z, br[1].w));
        uint4 v1 = make_uint4(pkh2(br[2].x, br[2].y), pkh2(br[2].z, br[2].w),
                              pkh2(br[3].x, br[3].y), pkh2(br[3].z, br[3].w));
        *(uint4*)bp = v0;
        *(uint4*)(bp + 8) = v1;
    };
    // ---- compute stage on buffer b ----
    auto comp = [&](int b) {
        unsigned a_base = (unsigned)__cvta_generic_to_shared(&As[b][0]);
        unsigned b_base = (unsigned)__cvta_generic_to_shared(&Bs[b][0]);
        int lr = lane & 15, lh = (lane >> 4) << 3;
#pragma unroll
        for (int ks = 0; ks < 32; ks += 16) {
            unsigned bf[2][4];
#pragma unroll
            for (int jj = 0; jj < 2; jj++) {
                unsigned addr = b_base + ((ks + lr) * BS_STRIDE + wn * 32 + jj * 16 + lh) * 2;
                asm volatile("ldmatrix.sync.aligned.m8n8.x4.trans.shared.b16 {%0,%1,%2,%3}, [%4];"
                             : "=r"(bf[jj][0]), "=r"(bf[jj][1]), "=r"(bf[jj][2]), "=r"(bf[jj][3])
                             : "r"(addr));
            }
#pragma unroll
            for (int i = 0; i < 4; i++) {
                unsigned af0, af1, af2, af3;
                unsigned addr = a_base + ((wm * 64 + i * 16 + lr) * AS_STRIDE + ks + lh) * 2;
                asm volatile("ldmatrix.sync.aligned.m8n8.x4.shared.b16 {%0,%1,%2,%3}, [%4];"
                             : "=r"(af0), "=r"(af1), "=r"(af2), "=r"(af3)
                             : "r"(addr));
#pragma unroll
                for (int jj = 0; jj < 2; jj++) {
#pragma unroll
                    for (int ns = 0; ns < 2; ns++) {
                        float* c = acc[i][jj * 2 + ns];
                        asm volatile("mma.sync.aligned.m16n8k16.row.col.f32.f16.f16.f32 "
                                     "{%0,%1,%2,%3}, {%4,%5,%6,%7}, {%8,%9}, {%0,%1,%2,%3};"
                                     : "+f"(c[0]), "+f"(c[1]), "+f"(c[2]), "+f"(c[3])
                                     : "r"(af0), "r"(af1), "r"(af2), "r"(af3),
                                       "r"(bf[jj][ns * 2]), "r"(bf[jj][ns * 2 + 1]));
                    }
                }
            }
        }
    };

    // ---- pipeline ----
    ldg(0);
    sts(0);
    __syncthreads();
    for (int it = 0; it < nit; it++) {
        int cur = it & 1;
        bool nxt = (it + 1 < nit);
        if (nxt) ldg(it + 1);
        comp(cur);
        __syncthreads();
        if (nxt) {
            sts(1 - cur);
            __syncthreads();
        }
    }

    // ---- attn-dot writeback (2 threads per row) ----
    ds += __shfl_xor_sync(0xFFFFFFFFu, ds, 1);
    dd += __shfl_xor_sync(0xFFFFFFFFu, dd, 1);
    if (blockIdx.x == 0 && (tid & 1) == 0 && gr_a < M) {
        g_as[gr_a] = ds;
        g_ad[gr_a] = dd;
    }

    // ---- epilogue: fp16 featH ----
#pragma unroll
    for (int i = 0; i < 4; i++) {
#pragma unroll
        for (int j = 0; j < 4; j++) {
            int row = row0 + wm * 64 + i * 16 + grp;
            int col = col0 + wn * 32 + j * 8 + t4 * 2;
            if (row < M)
                *(__half2*)(g_featH + (size_t)row * 256 + col) =
                    __floats2half2_rn(acc[i][j][0], acc[i][j][1]);
            if (row + 8 < M)
                *(__half2*)(g_featH + (size_t)(row + 8) * 256 + col) =
                    __floats2half2_rn(acc[i][j][2], acc[i][j][3]);
        }
    }
}

// ================= fused softmax + aggregate (warp per dst) =================
__device__ __forceinline__ void agg_edge(int sj, float aj, int lane, float acc[8]) {
    const uint4* hs = (const uint4*)(g_featH + (size_t)sj * H);
    uint4 q = hs[lane];
    const __half2* h2 = (const __half2*)&q;
#pragma unroll
    for (int c = 0; c < 4; c++) {
        float2 f = __half22float2(h2[c]);
        acc[c * 2 + 0] += aj * f.x;
        acc[c * 2 + 1] += aj * f.y;
    }
}

__device__ __forceinline__ void gat_attn_body(int warp, int lane, float acc[8]) {
    int beg = g_off[warp], end = g_off[warp + 1];
    int deg = end - beg;
    float ad = g_ad[warp];

    if (deg <= 32) {
        bool valid = lane < deg;
        int s = valid ? g_srcs[beg + lane] : 0;
        float e = -3.4e38f;
        if (valid) {
            e = g_as[s] + ad;
            e = (e > 0.f) ? e : NEG * e;
        }
        float m = e;
#pragma unroll
        for (int o = 16; o; o >>= 1) m = fmaxf(m, __shfl_xor_sync(0xFFFFFFFFu, m, o));
        float ex = valid ? expf(e - m) : 0.f;
        float denom = ex;
#pragma unroll
        for (int o = 16; o; o >>= 1) denom += __shfl_xor_sync(0xFFFFFFFFu, denom, o);
        float a = ex / fmaxf(denom, 1e-16f);
        for (int j = 0; j < deg; j++) {
            float aj = __shfl_sync(0xFFFFFFFFu, a, j);
            int   sj = __shfl_sync(0xFFFFFFFFu, s, j);
            agg_edge(sj, aj, lane, acc);
        }
    } else {
        float m = -3.4e38f;
        for (int i = beg + lane; i < end; i += 32) {
            float e = g_as[g_srcs[i]] + ad;
            e = (e > 0.f) ? e : NEG * e;
            m = fmaxf(m, e);
        }
#pragma unroll
        for (int o = 16; o; o >>= 1) m = fmaxf(m, __shfl_xor_sync(0xFFFFFFFFu, m, o));
        float denom = 0.f;
        for (int i = beg + lane; i < end; i += 32) {
            float e = g_as[g_srcs[i]] + ad;
            e = (e > 0.f) ? e : NEG * e;
            float ex = expf(e - m);
            g_e[i] = ex;
            denom += ex;
        }
#pragma unroll
        for (int o = 16; o; o >>= 1) denom += __shfl_xor_sync(0xFFFFFFFFu, denom, o);
        float inv = 1.f / fmaxf(denom, 1e-16f);
        for (int i0 = beg; i0 < end; i0 += 32) {
            int i = i0 + lane;
            float a = 0.f; int s = 0;
            if (i < end) { s = g_srcs[i]; a = g_e[i] * inv; }
            int cnt = min(32, end - i0);
            for (int j = 0; j < cnt; j++) {
                float aj = __shfl_sync(0xFFFFFFFFu, a, j);
                int   sj = __shfl_sync(0xFFFFFFFFu, s, j);
                agg_edge(sj, aj, lane, acc);
            }
        }
    }
}

// layers 1-2: write featB (fp32) for next GEMM
__global__ void gat_attn(const float* __restrict__ bias) {
    int warp = (blockIdx.x * blockDim.x + threadIdx.x) >> 5;
    int lane = threadIdx.x & 31;
    if (warp >= N_NODES) return;
    float acc[8] = {};
    gat_attn_body(warp, lane, acc);
    float* out = g_featB + (size_t)warp * H + lane * 8;
    const float* bp = bias + lane * 8;
    float4 o0, o1;
    o0.x = fmaxf(acc[0] + bp[0], 0.f); o0.y = fmaxf(acc[1] + bp[1], 0.f);
    o0.z = fmaxf(acc[2] + bp[2], 0.f); o0.w = fmaxf(acc[3] + bp[3], 0.f);
    o1.x = fmaxf(acc[4] + bp[4], 0.f); o1.y = fmaxf(acc[5] + bp[5], 0.f);
    o1.z = fmaxf(acc[6] + bp[6], 0.f); o1.w = fmaxf(acc[7] + bp[7], 0.f);
    *(float4*)out = o0;
    *(float4*)(out + 4) = o1;
}

// layer 3: pool directly into g_hg (skip featB entirely)
__global__ void gat_attn_pool(const float* __restrict__ bias, const int* __restrict__ batch) {
    int warp = (blockIdx.x * blockDim.x + threadIdx.x) >> 5;
    int lane = threadIdx.x & 31;
    if (warp >= N_NODES) return;
    float acc[8] = {};
    gat_attn_body(warp, lane, acc);
    int g = batch[warp];
    float* hg = g_hg + (size_t)g * H + lane * 8;
    const float* bp = bias + lane * 8;
#pragma unroll
    for (int c = 0; c < 8; c++)
        atomicAdd(&hg[c], fmaxf(acc[c] + bp[c], 0.f));
}

// ================= MLP head =================
__global__ void fc1_kernel(const float* __restrict__ w, const float* __restrict__ b) {
    __shared__ float sh[H];
    int g = blockIdx.x;
    float c = fmaxf(g_cnt[g], 1.f);
    sh[threadIdx.x] = g_hg[(size_t)g * H + threadIdx.x] / c;
    __syncthreads();
    int j = threadIdx.x;
    if (j < FC1) {
        float acc = b[j];
#pragma unroll 8
        for (int k = 0; k < H; k++)
            acc += sh[k] * w[(size_t)k * FC1 + j];
        g_fc1[(size_t)g * FC1 + j] = fmaxf(acc, 0.f);
    }
}

__global__ void fc2_kernel(const float* __restrict__ w, const float* __restrict__ b,
                           float* __restrict__ out) {
    int g = blockIdx.x;
    int o = threadIdx.x;
    if (o >= D_OUT) return;
    float acc = b[o];
#pragma unroll 4
    for (int k = 0; k < FC1; k++)
        acc += g_fc1[(size_t)g * FC1 + k] * w[(size_t)k * D_OUT + o];
    out[(size_t)g * D_OUT + o] = acc;
}

// ================= host =================
extern "C" void kernel_launch(void* const* d_in, const int* in_sizes, int n_in,
                              void* d_out, int out_size) {
    const float* x     = (const float*)d_in[0];
    const int*   ei    = (const int*)d_in[1];
    const int*   batch = (const int*)d_in[2];
    const float* W1 = (const float*)d_in[3];
    const float* a1s = (const float*)d_in[4];
    const float* a1d = (const float*)d_in[5];
    const float* b1 = (const float*)d_in[6];
    const float* W2 = (const float*)d_in[7];
    const float* a2s = (const float*)d_in[8];
    const float* a2d = (const float*)d_in[9];
    const float* b2 = (const float*)d_in[10];
    const float* W3 = (const float*)d_in[11];
    const float* a3s = (const float*)d_in[12];
    const float* a3d = (const float*)d_in[13];
    const float* b3 = (const float*)d_in[14];
    const float* fc1_w = (const float*)d_in[15];
    const float* fc1_b = (const float*)d_in[16];
    const float* fc2_w = (const float*)d_in[17];
    const float* fc2_b = (const float*)d_in[18];

    float* featB = nullptr;
    cudaGetSymbolAddress((void**)&featB, g_featB);

    dim3 gemmGrid(2, (N_NODES + 127) / 128);
    int edgeBlocks = (ET + 255) / 256;
    int nodeBlocksW = ((size_t)N_NODES * 32 + 255) / 256;

    // ---- CSR by dst + pooling counters ----
    zero_deg<<<(G_GRAPHS * H + 255) / 256, 256>>>();
    count_all<<<edgeBlocks, 256>>>(ei, batch);
    scan_local<<<NB_SCAN, 1024>>>();
    scan_bsums<<<1, 64>>>();
    scan_add<<<(N_NODES + 255) / 256, 256>>>();
    scatter_edges<<<edgeBlocks, 256>>>(ei);

    // ---- all attention projection vectors upfront ----
    wv_all<<<(F_IN + 2 * H) / 8, 256>>>(W1, a1s, a1d, W2, a2s, a2d, W3, a3s, a3d);

    // ---- layer 1 (K = F_IN) ----
    sgemm_tc<<<gemmGrid, 256>>>(x, W1, N_NODES, F_IN, 0);
    gat_attn<<<nodeBlocksW, 256>>>(b1);

    // ---- layer 2 ----
    sgemm_tc<<<gemmGrid, 256>>>(featB, W2, N_NODES, H, 1);
    gat_attn<<<nodeBlocksW, 256>>>(b2);

    // ---- layer 3 (pool fused) ----
    sgemm_tc<<<gemmGrid, 256>>>(featB, W3, N_NODES, H, 2);
    gat_attn_pool<<<nodeBlocksW, 256>>>(b3, batch);

    // ---- MLP head ----
    fc1_kernel<<<G_GRAPHS, H>>>(fc1_w, fc1_b);
    fc2_kernel<<<G_GRAPHS, 32>>>(fc2_w, fc2_b, (float*)d_out);
}

// round 10
// speedup vs baseline: 1.0286x; 1.0286x over previous
#include <cuda_runtime.h>
#include <cuda_fp16.h>
#include <math.h>

#define N_NODES 50000
#define N_EDGES 800000
#define ET (N_EDGES + N_NODES)   // edges + self loops = 850000
#define F_IN 128
#define H 256
#define G_GRAPHS 500
#define FC1 196
#define D_OUT 10
#define NEG 0.2f
#define NB_SCAN ((N_NODES + 1023) / 1024)   // 49 scan blocks

// ---------------- scratch (static device globals; no allocation) ----------------
__device__ float g_featB[(size_t)N_NODES * H];   // aggregated output / next-layer input
__device__ __align__(16) __half g_featH[(size_t)N_NODES * H]; // fp16 h for gather
__device__ float g_as[N_NODES];                  // x . (W a_s) per node
__device__ float g_ad[N_NODES];                  // x . (W a_d) per node
__device__ float g_wvs[3][H];                    // W @ a_s per layer
__device__ float g_wvd[3][H];                    // W @ a_d per layer
__device__ float g_e[ET];                        // per-edge exp(e - m) (slow path)
__device__ int   g_deg[N_NODES];
__device__ int   g_off[N_NODES + 1];             // CSR row offsets (by dst)
__device__ int   g_pos[N_NODES];
__device__ int   g_srcs[ET];                     // CSR column indices (src node)
__device__ int   g_bsum[NB_SCAN];
__device__ int   g_bpre[NB_SCAN];
__device__ float g_hg[G_GRAPHS * H];             // pooled per-graph sums
__device__ float g_cnt[G_GRAPHS];
__device__ float g_fc1[G_GRAPHS * FC1];

// ================= CSR build =================
__global__ void zero_deg() {
    int i = blockIdx.x * blockDim.x + threadIdx.x;
    if (i < N_NODES) g_deg[i] = 0;
    if (i < G_GRAPHS * H) g_hg[i] = 0.f;
    if (i < G_GRAPHS) g_cnt[i] = 0.f;
}

// merged: in-degree histogram + per-graph node counts
__global__ void count_all(const int* __restrict__ ei, const int* __restrict__ batch) {
    int e = blockIdx.x * blockDim.x + threadIdx.x;
    if (e < ET) {
        int d = (e < N_EDGES) ? ei[N_EDGES + e] : (e - N_EDGES);
        atomicAdd(&g_deg[d], 1);
    }
    if (e < N_NODES) atomicAdd(&g_cnt[batch[e]], 1.f);
}

__global__ __launch_bounds__(1024) void scan_local() {
    __shared__ int ws[32];
    int tid = threadIdx.x, lane = tid & 31, wid = tid >> 5;
    int i = blockIdx.x * 1024 + tid;
    int v = (i < N_NODES) ? g_deg[i] : 0;
    int incl = v;
#pragma unroll
    for (int o = 1; o < 32; o <<= 1) {
        int t = __shfl_up_sync(0xFFFFFFFFu, incl, o);
        if (lane >= o) incl += t;
    }
    if (lane == 31) ws[wid] = incl;
    __syncthreads();
    if (wid == 0) {
        int w = ws[lane];
#pragma unroll
        for (int o = 1; o < 32; o <<= 1) {
            int t = __shfl_up_sync(0xFFFFFFFFu, w, o);
            if (lane >= o) w += t;
        }
        ws[lane] = w;
    }
    __syncthreads();
    int excl = (wid ? ws[wid - 1] : 0) + incl - v;
    if (i < N_NODES) g_off[i] = excl;
    if (tid == 0) g_bsum[blockIdx.x] = ws[31];
}

__global__ void scan_bsums() {
    __shared__ int sh[64];
    int tid = threadIdx.x;
    int v = (tid < NB_SCAN) ? g_bsum[tid] : 0;
    sh[tid] = v;
    __syncthreads();
#pragma unroll
    for (int o = 1; o < 64; o <<= 1) {
        int t = (tid >= o) ? sh[tid - o] : 0;
        __syncthreads();
        sh[tid] += t;
        __syncthreads();
    }
    if (tid < NB_SCAN) g_bpre[tid] = sh[tid] - v;
}

__global__ void scan_add() {
    int i = blockIdx.x * blockDim.x + threadIdx.x;
    if (i == 0) g_off[N_NODES] = ET;
    if (i < N_NODES) {
        int o = g_off[i] + g_bpre[i >> 10];
        g_off[i] = o;
        g_pos[i] = o;
    }
}

__global__ void scatter_edges(const int* __restrict__ ei) {
    int e = blockIdx.x * blockDim.x + threadIdx.x;
    if (e >= ET) return;
    int s, d;
    if (e < N_EDGES) { s = ei[e]; d = ei[N_EDGES + e]; }
    else             { s = d = e - N_EDGES; }
    int idx = atomicAdd(&g_pos[d], 1);
    g_srcs[idx] = s;
}

// ================= wv for ALL layers upfront (warp per output k) =================
__global__ void wv_all(const float* __restrict__ W1, const float* __restrict__ a1s, const float* __restrict__ a1d,
                       const float* __restrict__ W2, const float* __restrict__ a2s, const float* __restrict__ a2d,
                       const float* __restrict__ W3, const float* __restrict__ a3s, const float* __restrict__ a3d) {
    int w = (blockIdx.x * blockDim.x + threadIdx.x) >> 5;   // 0..639
    int lane = threadIdx.x & 31;
    if (w >= F_IN + 2 * H) return;
    int l, k;
    const float *W, *as_, *ad_;
    if (w < F_IN)          { l = 0; k = w;           W = W1; as_ = a1s; ad_ = a1d; }
    else if (w < F_IN + H) { l = 1; k = w - F_IN;    W = W2; as_ = a2s; ad_ = a2d; }
    else                   { l = 2; k = w - F_IN - H; W = W3; as_ = a3s; ad_ = a3d; }
    const float4* wr = (const float4*)(W + (size_t)k * H);
    const float4* sa = (const float4*)as_;
    const float4* da = (const float4*)ad_;
    float4 w0 = wr[lane], w1 = wr[lane + 32];
    float4 s0 = sa[lane], s1 = sa[lane + 32];
    float4 d0 = da[lane], d1 = da[lane + 32];
    float s = w0.x * s0.x + w0.y * s0.y + w0.z * s0.z + w0.w * s0.w
            + w1.x * s1.x + w1.y * s1.y + w1.z * s1.z + w1.w * s1.w;
    float d = w0.x * d0.x + w0.y * d0.y + w0.z * d0.z + w0.w * d0.w
            + w1.x * d1.x + w1.y * d1.y + w1.z * d1.z + w1.w * d1.w;
#pragma unroll
    for (int o = 16; o; o >>= 1) {
        s += __shfl_down_sync(0xFFFFFFFFu, s, o);
        d += __shfl_down_sync(0xFFFFFFFFu, d, o);
    }
    if (lane == 0) { g_wvs[l][k] = s; g_wvd[l][k] = d; }
}

// ================= fp16 TC GEMM (m16n8k16, ldmatrix, double-buffered) =================
__device__ __forceinline__ unsigned pkh2(float a, float b) {
    __half2 h = __floats2half2_rn(a, b);
    return *(unsigned*)&h;
}

#define AS_STRIDE 40    // halves per A row (32 + 8 pad)
#define BS_STRIDE 136   // halves per B k-row (128 + 8 pad)

__global__ __launch_bounds__(256) void sgemm_tc(const float* __restrict__ A,
                                                const float* __restrict__ W,
                                                int M, int K, int layer) {
    __shared__ __half As[2][128 * AS_STRIDE];
    __shared__ __half Bs[2][32 * BS_STRIDE];

    int tid = threadIdx.x;
    int wid = tid >> 5, lane = tid & 31;
    int grp = lane >> 2, t4 = lane & 3;
    int wm = wid >> 2, wn = wid & 3;           // warp grid 2x4, warp tile 64x32
    int row0 = blockIdx.y * 128;
    int col0 = blockIdx.x * 128;

    int arow = tid >> 1;                       // 0..127
    int akoff = (tid & 1) * 16;                // 0 or 16
    int brow = tid >> 3;                       // 0..31
    int bnoff = (tid & 7) * 16;                // 0..112

    const float* wvs = g_wvs[layer];
    const float* wvd = g_wvd[layer];

    float acc[4][4][4] = {};
    float ds = 0.f, dd = 0.f;
    float4 ar[4], br[4];
    int gr_a = row0 + arow;

    int nit = K >> 5;

    auto ldg = [&](int it) {
        int k0 = it * 32;
#pragma unroll
        for (int c = 0; c < 4; c++) {
            ar[c] = (gr_a < M) ? *(const float4*)(A + (size_t)gr_a * K + k0 + akoff + c * 4)
                               : make_float4(0.f, 0.f, 0.f, 0.f);
            br[c] = *(const float4*)(W + (size_t)(k0 + brow) * 256 + col0 + bnoff + c * 4);
            float4 wv = *(const float4*)(wvs + k0 + akoff + c * 4);
            float4 wd = *(const float4*)(wvd + k0 + akoff + c * 4);
            ds += ar[c].x * wv.x + ar[c].y * wv.y + ar[c].z * wv.z + ar[c].w * wv.w;
            dd += ar[c].x * wd.x + ar[c].y * wd.y + ar[c].z * wd.z + ar[c].w * wd.w;
        }
    };
    auto sts = [&](int buf) {
        __half* ap = &As[buf][arow * AS_STRIDE + akoff];
        uint4 u0 = make_uint4(pkh2(ar[0].x, ar[0].y), pkh2(ar[0].z, ar[0].w),
                              pkh2(ar[1].x, ar[1].y), pkh2(ar[1].z, ar[1].w));
        uint4 u1 = make_uint4(pkh2(ar[2].x, ar[2].y), pkh2(ar[2].z, ar[2].w),
                              pkh2(ar[3].x, ar[3].y), pkh2(ar[3].z, ar[3].w));
        *(uint4*)ap = u0;
        *(uint4*)(ap + 8) = u1;
        __half* bp = &Bs[buf][brow * BS_STRIDE + bnoff];
        uint4 v0 = make_uint4(pkh2(br[0].x, br[0].y), pkh2(br[0].z, br[0].w),
                              pkh2(br[1].x, br[1].y), pkh2(br[1].z, br[1].w));
        uint4 v1 = make_uint4(pkh2(br[2].x, br[2].y), pkh2(br[2].z, br[2].w),
                              pkh2(br[3].x, br[3].y), pkh2(br[3].z, br[3].w));
        *(uint4*)bp = v0;
        *(uint4*)(bp + 8) = v1;
    };
    auto comp = [&](int b) {
        unsigned a_base = (unsigned)__cvta_generic_to_shared(&As[b][0]);
        unsigned b_base = (unsigned)__cvta_generic_to_shared(&Bs[b][0]);
        int lr = lane & 15, lh = (lane >> 4) << 3;
#pragma unroll
        for (int ks = 0; ks < 32; ks += 16) {
            unsigned bf[2][4];
#pragma unroll
            for (int jj = 0; jj < 2; jj++) {
                unsigned addr = b_base + ((ks + lr) * BS_STRIDE + wn * 32 + jj * 16 + lh) * 2;
                asm volatile("ldmatrix.sync.aligned.m8n8.x4.trans.shared.b16 {%0,%1,%2,%3}, [%4];"
                             : "=r"(bf[jj][0]), "=r"(bf[jj][1]), "=r"(bf[jj][2]), "=r"(bf[jj][3])
                             : "r"(addr));
            }
#pragma unroll
            for (int i = 0; i < 4; i++) {
                unsigned af0, af1, af2, af3;
                unsigned addr = a_base + ((wm * 64 + i * 16 + lr) * AS_STRIDE + ks + lh) * 2;
                asm volatile("ldmatrix.sync.aligned.m8n8.x4.shared.b16 {%0,%1,%2,%3}, [%4];"
                             : "=r"(af0), "=r"(af1), "=r"(af2), "=r"(af3)
                             : "r"(addr));
#pragma unroll
                for (int jj = 0; jj < 2; jj++) {
#pragma unroll
                    for (int ns = 0; ns < 2; ns++) {
                        float* c = acc[i][jj * 2 + ns];
                        asm volatile("mma.sync.aligned.m16n8k16.row.col.f32.f16.f16.f32 "
                                     "{%0,%1,%2,%3}, {%4,%5,%6,%7}, {%8,%9}, {%0,%1,%2,%3};"
                                     : "+f"(c[0]), "+f"(c[1]), "+f"(c[2]), "+f"(c[3])
                                     : "r"(af0), "r"(af1), "r"(af2), "r"(af3),
                                       "r"(bf[jj][ns * 2]), "r"(bf[jj][ns * 2 + 1]));
                    }
                }
            }
        }
    };

    ldg(0);
    sts(0);
    __syncthreads();
    for (int it = 0; it < nit; it++) {
        int cur = it & 1;
        bool nxt = (it + 1 < nit);
        if (nxt) ldg(it + 1);
        comp(cur);
        __syncthreads();
        if (nxt) {
            sts(1 - cur);
            __syncthreads();
        }
    }

    ds += __shfl_xor_sync(0xFFFFFFFFu, ds, 1);
    dd += __shfl_xor_sync(0xFFFFFFFFu, dd, 1);
    if (blockIdx.x == 0 && (tid & 1) == 0 && gr_a < M) {
        g_as[gr_a] = ds;
        g_ad[gr_a] = dd;
    }

#pragma unroll
    for (int i = 0; i < 4; i++) {
#pragma unroll
        for (int j = 0; j < 4; j++) {
            int row = row0 + wm * 64 + i * 16 + grp;
            int col = col0 + wn * 32 + j * 8 + t4 * 2;
            if (row < M)
                *(__half2*)(g_featH + (size_t)row * 256 + col) =
                    __floats2half2_rn(acc[i][j][0], acc[i][j][1]);
            if (row + 8 < M)
                *(__half2*)(g_featH + (size_t)(row + 8) * 256 + col) =
                    __floats2half2_rn(acc[i][j][2], acc[i][j][3]);
        }
    }
}

// ================= fused softmax + aggregate (warp per dst) =================
__device__ __forceinline__ void agg_edge(int sj, float aj, int lane, float acc[8]) {
    const uint4* hs = (const uint4*)(g_featH + (size_t)sj * H);
    uint4 q = hs[lane];
    const __half2* h2 = (const __half2*)&q;
#pragma unroll
    for (int c = 0; c < 4; c++) {
        float2 f = __half22float2(h2[c]);
        acc[c * 2 + 0] += aj * f.x;
        acc[c * 2 + 1] += aj * f.y;
    }
}

// unrolled-by-2: two independent 512B gathers in flight
__device__ __forceinline__ void agg_sweep(float a, int s, int cnt, int lane, float acc[8]) {
    int j = 0;
    for (; j + 2 <= cnt; j += 2) {
        float aj0 = __shfl_sync(0xFFFFFFFFu, a, j);
        int   sj0 = __shfl_sync(0xFFFFFFFFu, s, j);
        float aj1 = __shfl_sync(0xFFFFFFFFu, a, j + 1);
        int   sj1 = __shfl_sync(0xFFFFFFFFu, s, j + 1);
        uint4 q0 = ((const uint4*)(g_featH + (size_t)sj0 * H))[lane];
        uint4 q1 = ((const uint4*)(g_featH + (size_t)sj1 * H))[lane];
        const __half2* h0 = (const __half2*)&q0;
        const __half2* h1 = (const __half2*)&q1;
#pragma unroll
        for (int c = 0; c < 4; c++) {
            float2 f0 = __half22float2(h0[c]);
            float2 f1 = __half22float2(h1[c]);
            acc[c * 2 + 0] += aj0 * f0.x + aj1 * f1.x;
            acc[c * 2 + 1] += aj0 * f0.y + aj1 * f1.y;
        }
    }
    if (j < cnt) {
        float aj = __shfl_sync(0xFFFFFFFFu, a, j);
        int   sj = __shfl_sync(0xFFFFFFFFu, s, j);
        agg_edge(sj, aj, lane, acc);
    }
}

__device__ __forceinline__ void gat_attn_body(int warp, int lane, float acc[8]) {
    int beg = g_off[warp], end = g_off[warp + 1];
    int deg = end - beg;
    float ad = g_ad[warp];

    if (deg <= 32) {
        bool valid = lane < deg;
        int s = valid ? g_srcs[beg + lane] : 0;
        float e = -3.4e38f;
        if (valid) {
            e = g_as[s] + ad;
            e = (e > 0.f) ? e : NEG * e;
        }
        float m = e;
#pragma unroll
        for (int o = 16; o; o >>= 1) m = fmaxf(m, __shfl_xor_sync(0xFFFFFFFFu, m, o));
        float ex = valid ? expf(e - m) : 0.f;
        float denom = ex;
#pragma unroll
        for (int o = 16; o; o >>= 1) denom += __shfl_xor_sync(0xFFFFFFFFu, denom, o);
        float a = ex / fmaxf(denom, 1e-16f);
        agg_sweep(a, s, deg, lane, acc);
    } else {
        float m = -3.4e38f;
        for (int i = beg + lane; i < end; i += 32) {
            float e = g_as[g_srcs[i]] + ad;
            e = (e > 0.f) ? e : NEG * e;
            m = fmaxf(m, e);
        }
#pragma unroll
        for (int o = 16; o; o >>= 1) m = fmaxf(m, __shfl_xor_sync(0xFFFFFFFFu, m, o));
        float denom = 0.f;
        for (int i = beg + lane; i < end; i += 32) {
            float e = g_as[g_srcs[i]] + ad;
            e = (e > 0.f) ? e : NEG * e;
            float ex = expf(e - m);
            g_e[i] = ex;
            denom += ex;
        }
#pragma unroll
        for (int o = 16; o; o >>= 1) denom += __shfl_xor_sync(0xFFFFFFFFu, denom, o);
        float inv = 1.f / fmaxf(denom, 1e-16f);
        for (int i0 = beg; i0 < end; i0 += 32) {
            int i = i0 + lane;
            float a = 0.f; int s = 0;
            if (i < end) { s = g_srcs[i]; a = g_e[i] * inv; }
            agg_sweep(a, s, min(32, end - i0), lane, acc);
        }
    }
}

// layers 1-2: write featB (fp32) for next GEMM
__global__ void gat_attn(const float* __restrict__ bias) {
    int warp = (blockIdx.x * blockDim.x + threadIdx.x) >> 5;
    int lane = threadIdx.x & 31;
    if (warp >= N_NODES) return;
    float acc[8] = {};
    gat_attn_body(warp, lane, acc);
    float* out = g_featB + (size_t)warp * H + lane * 8;
    const float* bp = bias + lane * 8;
    float4 o0, o1;
    o0.x = fmaxf(acc[0] + bp[0], 0.f); o0.y = fmaxf(acc[1] + bp[1], 0.f);
    o0.z = fmaxf(acc[2] + bp[2], 0.f); o0.w = fmaxf(acc[3] + bp[3], 0.f);
    o1.x = fmaxf(acc[4] + bp[4], 0.f); o1.y = fmaxf(acc[5] + bp[5], 0.f);
    o1.z = fmaxf(acc[6] + bp[6], 0.f); o1.w = fmaxf(acc[7] + bp[7], 0.f);
    *(float4*)out = o0;
    *(float4*)(out + 4) = o1;
}

// layer 3: pool directly into g_hg
__global__ void gat_attn_pool(const float* __restrict__ bias, const int* __restrict__ batch) {
    int warp = (blockIdx.x * blockDim.x + threadIdx.x) >> 5;
    int lane = threadIdx.x & 31;
    if (warp >= N_NODES) return;
    float acc[8] = {};
    gat_attn_body(warp, lane, acc);
    int g = batch[warp];
    float* hg = g_hg + (size_t)g * H + lane * 8;
    const float* bp = bias + lane * 8;
#pragma unroll
    for (int c = 0; c < 8; c++)
        atomicAdd(&hg[c], fmaxf(acc[c] + bp[c], 0.f));
}

// ================= MLP head =================
__global__ void fc1_kernel(const float* __restrict__ w, const float* __restrict__ b) {
    __shared__ float sh[H];
    int g = blockIdx.x;
    float c = fmaxf(g_cnt[g], 1.f);
    sh[threadIdx.x] = g_hg[(size_t)g * H + threadIdx.x] / c;
    __syncthreads();
    int j = threadIdx.x;
    if (j < FC1) {
        float acc = b[j];
#pragma unroll 8
        for (int k = 0; k < H; k++)
            acc += sh[k] * w[(size_t)k * FC1 + j];
        g_fc1[(size_t)g * FC1 + j] = fmaxf(acc, 0.f);
    }
}

__global__ void fc2_kernel(const float* __restrict__ w, const float* __restrict__ b,
                           float* __restrict__ out) {
    int g = blockIdx.x;
    int o = threadIdx.x;
    if (o >= D_OUT) return;
    float acc = b[o];
#pragma unroll 4
    for (int k = 0; k < FC1; k++)
        acc += g_fc1[(size_t)g * FC1 + k] * w[(size_t)k * D_OUT + o];
    out[(size_t)g * D_OUT + o] = acc;
}

// ================= host =================
extern "C" void kernel_launch(void* const* d_in, const int* in_sizes, int n_in,
                              void* d_out, int out_size) {
    const float* x     = (const float*)d_in[0];
    const int*   ei    = (const int*)d_in[1];
    const int*   batch = (const int*)d_in[2];
    const float* W1 = (const float*)d_in[3];
    const float* a1s = (const float*)d_in[4];
    const float* a1d = (const float*)d_in[5];
    const float* b1 = (const float*)d_in[6];
    const float* W2 = (const float*)d_in[7];
    const float* a2s = (const float*)d_in[8];
    const float* a2d = (const float*)d_in[9];
    const float* b2 = (const float*)d_in[10];
    const float* W3 = (const float*)d_in[11];
    const float* a3s = (const float*)d_in[12];
    const float* a3d = (const float*)d_in[13];
    const float* b3 = (const float*)d_in[14];
    const float* fc1_w = (const float*)d_in[15];
    const float* fc1_b = (const float*)d_in[16];
    const float* fc2_w = (const float*)d_in[17];
    const float* fc2_b = (const float*)d_in[18];

    float* featB = nullptr;
    cudaGetSymbolAddress((void**)&featB, g_featB);

    // persistent side stream + events (host objects; created once, reused)
    static cudaStream_t s2 = nullptr;
    static cudaEvent_t evA = nullptr, evB = nullptr;
    if (!s2) {
        cudaStreamCreateWithFlags(&s2, cudaStreamNonBlocking);
        cudaEventCreateWithFlags(&evA, cudaEventDisableTiming);
        cudaEventCreateWithFlags(&evB, cudaEventDisableTiming);
    }

    dim3 gemmGrid(2, (N_NODES + 127) / 128);
    int edgeBlocks = (ET + 255) / 256;
    int nodeBlocksW = ((size_t)N_NODES * 32 + 255) / 256;

    // ---- main stream: zero + counts, then wv + layer-1 GEMM (independent of CSR) ----
    zero_deg<<<(G_GRAPHS * H + 255) / 256, 256>>>();                           // #1
    count_all<<<edgeBlocks, 256>>>(ei, batch);                                 // #2
    cudaEventRecord(evA, 0);   // CSR chain may start once counts are done

    wv_all<<<(F_IN + 2 * H) / 8, 256>>>(W1, a1s, a1d, W2, a2s, a2d, W3, a3s, a3d); // #3
    sgemm_tc<<<gemmGrid, 256>>>(x, W1, N_NODES, F_IN, 0);                      // #4 (profiled)

    // ---- side stream: scan + scatter, concurrent with wv+GEMM1 ----
    cudaStreamWaitEvent(s2, evA, 0);
    scan_local<<<NB_SCAN, 1024, 0, s2>>>();
    scan_bsums<<<1, 64, 0, s2>>>();
    scan_add<<<(N_NODES + 255) / 256, 256, 0, s2>>>();
    scatter_edges<<<edgeBlocks, 256, 0, s2>>>(ei);
    cudaEventRecord(evB, s2);
    cudaStreamWaitEvent(0, evB, 0);   // join before attention

    // ---- layer 1 attention ----
    gat_attn<<<nodeBlocksW, 256>>>(b1);

    // ---- layer 2 ----
    sgemm_tc<<<gemmGrid, 256>>>(featB, W2, N_NODES, H, 1);
    gat_attn<<<nodeBlocksW, 256>>>(b2);

    // ---- layer 3 (pool fused) ----
    sgemm_tc<<<gemmGrid, 256>>>(featB, W3, N_NODES, H, 2);
    gat_attn_pool<<<nodeBlocksW, 256>>>(b3, batch);

    // ---- MLP head ----
    fc1_kernel<<<G_GRAPHS, H>>>(fc1_w, fc1_b);
    fc2_kernel<<<G_GRAPHS, 32>>>(fc2_w, fc2_b, (float*)d_out);
}

// round 11
// speedup vs baseline: 1.1801x; 1.1472x over previous
#include <cuda_runtime.h>
#include <cuda_fp16.h>
#include <math.h>

#define N_NODES 50000
#define N_EDGES 800000
#define ET (N_EDGES + N_NODES)   // edges + self loops = 850000
#define F_IN 128
#define H 256
#define G_GRAPHS 500
#define FC1 196
#define D_OUT 10
#define NEG 0.2f
#define NB_SCAN ((N_NODES + 1023) / 1024)   // 49 scan blocks

// ---------------- scratch (static device globals; no allocation) ----------------
__device__ __align__(16) __half g_featH[(size_t)N_NODES * H];   // h = A@W (fp16, GEMM out)
__device__ __align__(16) __half g_featBH[(size_t)N_NODES * H];  // attention out (fp16, next A)
__device__ __align__(16) __half g_x16[(size_t)N_NODES * F_IN];  // fp16 copy of x
__device__ __align__(16) __half g_W16[3][H * H];                // fp16 weights (W1 uses 128 rows)
__device__ float g_as[N_NODES];                  // h . a_s per node (combined)
__device__ float g_ad[N_NODES];                  // h . a_d per node
__device__ float g_dsp[2][N_NODES];              // per-colblock dot partials (s)
__device__ float g_ddp[2][N_NODES];              // per-colblock dot partials (d)
__device__ float g_e[ET];                        // per-edge exp(e - m) (slow path)
__device__ int   g_deg[N_NODES];
__device__ int   g_off[N_NODES + 1];             // CSR row offsets (by dst)
__device__ int   g_pos[N_NODES];
__device__ int   g_srcs[ET];                     // CSR column indices (src node)
__device__ int   g_bsum[NB_SCAN];
__device__ int   g_bpre[NB_SCAN];
__device__ float g_hg[G_GRAPHS * H];             // pooled per-graph sums
__device__ float g_cnt[G_GRAPHS];
__device__ float g_fc1[G_GRAPHS * FC1];

// ================= CSR build =================
__global__ void zero_deg() {
    int i = blockIdx.x * blockDim.x + threadIdx.x;
    if (i < N_NODES) g_deg[i] = 0;
    if (i < G_GRAPHS * H) g_hg[i] = 0.f;
    if (i < G_GRAPHS) g_cnt[i] = 0.f;
}

__global__ void count_all(const int* __restrict__ ei, const int* __restrict__ batch) {
    int e = blockIdx.x * blockDim.x + threadIdx.x;
    if (e < ET) {
        int d = (e < N_EDGES) ? ei[N_EDGES + e] : (e - N_EDGES);
        atomicAdd(&g_deg[d], 1);
    }
    if (e < N_NODES) atomicAdd(&g_cnt[batch[e]], 1.f);
}

__global__ __launch_bounds__(1024) void scan_local() {
    __shared__ int ws[32];
    int tid = threadIdx.x, lane = tid & 31, wid = tid >> 5;
    int i = blockIdx.x * 1024 + tid;
    int v = (i < N_NODES) ? g_deg[i] : 0;
    int incl = v;
#pragma unroll
    for (int o = 1; o < 32; o <<= 1) {
        int t = __shfl_up_sync(0xFFFFFFFFu, incl, o);
        if (lane >= o) incl += t;
    }
    if (lane == 31) ws[wid] = incl;
    __syncthreads();
    if (wid == 0) {
        int w = ws[lane];
#pragma unroll
        for (int o = 1; o < 32; o <<= 1) {
            int t = __shfl_up_sync(0xFFFFFFFFu, w, o);
            if (lane >= o) w += t;
        }
        ws[lane] = w;
    }
    __syncthreads();
    int excl = (wid ? ws[wid - 1] : 0) + incl - v;
    if (i < N_NODES) g_off[i] = excl;
    if (tid == 0) g_bsum[blockIdx.x] = ws[31];
}

__global__ void scan_bsums() {
    __shared__ int sh[64];
    int tid = threadIdx.x;
    int v = (tid < NB_SCAN) ? g_bsum[tid] : 0;
    sh[tid] = v;
    __syncthreads();
#pragma unroll
    for (int o = 1; o < 64; o <<= 1) {
        int t = (tid >= o) ? sh[tid - o] : 0;
        __syncthreads();
        sh[tid] += t;
        __syncthreads();
    }
    if (tid < NB_SCAN) g_bpre[tid] = sh[tid] - v;
}

__global__ void scan_add() {
    int i = blockIdx.x * blockDim.x + threadIdx.x;
    if (i == 0) g_off[N_NODES] = ET;
    if (i < N_NODES) {
        int o = g_off[i] + g_bpre[i >> 10];
        g_off[i] = o;
        g_pos[i] = o;
    }
}

__global__ void scatter_edges(const int* __restrict__ ei) {
    int e = blockIdx.x * blockDim.x + threadIdx.x;
    if (e >= ET) return;
    int s, d;
    if (e < N_EDGES) { s = ei[e]; d = ei[N_EDGES + e]; }
    else             { s = d = e - N_EDGES; }
    int idx = atomicAdd(&g_pos[d], 1);
    g_srcs[idx] = s;
}

// ================= fp32 -> fp16 conversion of x and all weights =================
#define X_ELEMS (N_NODES * F_IN)          // 6,400,000
#define W1_ELEMS (F_IN * H)               // 32,768
#define W23_ELEMS (H * H)                 // 65,536
#define CONV_TOT (X_ELEMS + W1_ELEMS + 2 * W23_ELEMS)

__global__ void conv_all(const float* __restrict__ x, const float* __restrict__ W1,
                         const float* __restrict__ W2, const float* __restrict__ W3) {
    int i4 = blockIdx.x * blockDim.x + threadIdx.x;   // float4 index
    size_t off = (size_t)i4 * 4;
    if (off >= CONV_TOT) return;
    const float* src;
    __half* dst;
    if (off < X_ELEMS)                       { src = x + off;  dst = g_x16 + off; }
    else if (off < X_ELEMS + W1_ELEMS)       { size_t o = off - X_ELEMS;              src = W1 + o; dst = g_W16[0] + o; }
    else if (off < X_ELEMS + W1_ELEMS + W23_ELEMS) { size_t o = off - X_ELEMS - W1_ELEMS; src = W2 + o; dst = g_W16[1] + o; }
    else                                     { size_t o = off - X_ELEMS - W1_ELEMS - W23_ELEMS; src = W3 + o; dst = g_W16[2] + o; }
    float4 v = *(const float4*)src;
    __half2* d2 = (__half2*)dst;
    d2[0] = __floats2half2_rn(v.x, v.y);
    d2[1] = __floats2half2_rn(v.z, v.w);
}

// ================= pure-fp16 TC GEMM (cp.async, m16n8k16, ldmatrix) =================
// featH(fp16)[M,256] = A16[M,K] @ W16[K,256]; dot partials vs a_s/a_d from fp32 acc.
#define AS_STRIDE 40    // halves per A row (32 + 8 pad); 80B, 16B-aligned rows
#define BS_STRIDE 136   // halves per B k-row (128 + 8 pad); 272B, 16B-aligned rows

__device__ __forceinline__ void cp16(unsigned dst, const void* src) {
    asm volatile("cp.async.cg.shared.global [%0], [%1], 16;" :: "r"(dst), "l"(src));
}

__global__ __launch_bounds__(256, 2) void sgemm_tc(const __half* __restrict__ A,
                                                   const __half* __restrict__ Wl,
                                                   const float* __restrict__ avs,
                                                   const float* __restrict__ avd,
                                                   int M, int K) {
    __shared__ __half As[2][128 * AS_STRIDE];
    __shared__ __half Bs[2][32 * BS_STRIDE];
    __shared__ float sds[128], sdd[128];

    int tid = threadIdx.x;
    int wid = tid >> 5, lane = tid & 31;
    int grp = lane >> 2, t4 = lane & 3;
    int wm = wid >> 2, wn = wid & 3;           // warp grid 2x4, warp tile 64x32
    int row0 = blockIdx.y * 128;
    int col0 = blockIdx.x * 128;

    // cp.async chunk assignment: 2 chunks each for A and B per thread
    int ac0 = tid * 2;                         // A chunk ids (512 total): row=c>>2, koff=(c&3)*8
    int bc0 = tid * 2;                         // B chunk ids (512 total): krow=c>>4, noff=(c&15)*8

    float acc[4][4][4] = {};
    int nit = K >> 5;

    if (tid < 128) { sds[tid] = 0.f; sdd[tid] = 0.f; }

    auto issue = [&](int it) {
        int k0 = it * 32;
        int buf = it & 1;
        unsigned a_base = (unsigned)__cvta_generic_to_shared(&As[buf][0]);
        unsigned b_base = (unsigned)__cvta_generic_to_shared(&Bs[buf][0]);
#pragma unroll
        for (int q = 0; q < 2; q++) {
            int c = ac0 + q;
            int row = c >> 2, koff = (c & 3) * 8;
            if (row0 + row < M)
                cp16(a_base + (row * AS_STRIDE + koff) * 2,
                     A + (size_t)(row0 + row) * K + k0 + koff);
            int cb = bc0 + q;
            int krow = cb >> 4, noff = (cb & 15) * 8;
            cp16(b_base + (krow * BS_STRIDE + noff) * 2,
                 Wl + (size_t)(k0 + krow) * 256 + col0 + noff);
        }
        asm volatile("cp.async.commit_group;");
    };

    auto comp = [&](int b) {
        unsigned a_base = (unsigned)__cvta_generic_to_shared(&As[b][0]);
        unsigned b_base = (unsigned)__cvta_generic_to_shared(&Bs[b][0]);
        int lr = lane & 15, lh = (lane >> 4) << 3;
#pragma unroll
        for (int ks = 0; ks < 32; ks += 16) {
            unsigned bf[2][4];
#pragma unroll
            for (int jj = 0; jj < 2; jj++) {
                unsigned addr = b_base + ((ks + lr) * BS_STRIDE + wn * 32 + jj * 16 + lh) * 2;
                asm volatile("ldmatrix.sync.aligned.m8n8.x4.trans.shared.b16 {%0,%1,%2,%3}, [%4];"
                             : "=r"(bf[jj][0]), "=r"(bf[jj][1]), "=r"(bf[jj][2]), "=r"(bf[jj][3])
                             : "r"(addr));
            }
#pragma unroll
            for (int i = 0; i < 4; i++) {
                unsigned af0, af1, af2, af3;
                unsigned addr = a_base + ((wm * 64 + i * 16 + lr) * AS_STRIDE + ks + lh) * 2;
                asm volatile("ldmatrix.sync.aligned.m8n8.x4.shared.b16 {%0,%1,%2,%3}, [%4];"
                             : "=r"(af0), "=r"(af1), "=r"(af2), "=r"(af3)
                             : "r"(addr));
#pragma unroll
                for (int jj = 0; jj < 2; jj++) {
#pragma unroll
                    for (int ns = 0; ns < 2; ns++) {
                        float* c = acc[i][jj * 2 + ns];
                        asm volatile("mma.sync.aligned.m16n8k16.row.col.f32.f16.f16.f32 "
                                     "{%0,%1,%2,%3}, {%4,%5,%6,%7}, {%8,%9}, {%0,%1,%2,%3};"
                                     : "+f"(c[0]), "+f"(c[1]), "+f"(c[2]), "+f"(c[3])
                                     : "r"(af0), "r"(af1), "r"(af2), "r"(af3),
                                       "r"(bf[jj][ns * 2]), "r"(bf[jj][ns * 2 + 1]));
                    }
                }
            }
        }
    };

    // ---- pipelined mainloop ----
    issue(0);
    for (int it = 0; it < nit; it++) {
        if (it + 1 < nit) {
            issue(it + 1);
            asm volatile("cp.async.wait_group 1;");
        } else {
            asm volatile("cp.async.wait_group 0;");
        }
        __syncthreads();
        comp(it & 1);
        __syncthreads();
    }

    // ---- attention-dot epilogue (fp32-exact from acc) ----
    float a_s_r[8], a_d_r[8];
#pragma unroll
    for (int j = 0; j < 4; j++) {
        int col = col0 + wn * 32 + j * 8 + t4 * 2;
        a_s_r[j * 2 + 0] = avs[col];     a_s_r[j * 2 + 1] = avs[col + 1];
        a_d_r[j * 2 + 0] = avd[col];     a_d_r[j * 2 + 1] = avd[col + 1];
    }
#pragma unroll
    for (int i = 0; i < 4; i++) {
        float ps0 = 0.f, pd0 = 0.f, ps1 = 0.f, pd1 = 0.f;
#pragma unroll
        for (int j = 0; j < 4; j++) {
            ps0 += acc[i][j][0] * a_s_r[j * 2] + acc[i][j][1] * a_s_r[j * 2 + 1];
            pd0 += acc[i][j][0] * a_d_r[j * 2] + acc[i][j][1] * a_d_r[j * 2 + 1];
            ps1 += acc[i][j][2] * a_s_r[j * 2] + acc[i][j][3] * a_s_r[j * 2 + 1];
            pd1 += acc[i][j][2] * a_d_r[j * 2] + acc[i][j][3] * a_d_r[j * 2 + 1];
        }
        int rl = wm * 64 + i * 16 + grp;
        atomicAdd(&sds[rl], ps0);     atomicAdd(&sdd[rl], pd0);
        atomicAdd(&sds[rl + 8], ps1); atomicAdd(&sdd[rl + 8], pd1);
    }
    __syncthreads();
    if (tid < 128) {
        int row = row0 + tid;
        if (row < M) {
            g_dsp[blockIdx.x][row] = sds[tid];
            g_ddp[blockIdx.x][row] = sdd[tid];
        }
    }

    // ---- fp16 featH store ----
#pragma unroll
    for (int i = 0; i < 4; i++) {
#pragma unroll
        for (int j = 0; j < 4; j++) {
            int row = row0 + wm * 64 + i * 16 + grp;
            int col = col0 + wn * 32 + j * 8 + t4 * 2;
            if (row < M)
                *(__half2*)(g_featH + (size_t)row * 256 + col) =
                    __floats2half2_rn(acc[i][j][0], acc[i][j][1]);
            if (row + 8 < M)
                *(__half2*)(g_featH + (size_t)(row + 8) * 256 + col) =
                    __floats2half2_rn(acc[i][j][2], acc[i][j][3]);
        }
    }
}

// ================= combine per-colblock dot partials =================
__global__ void combine_dots() {
    int i = blockIdx.x * blockDim.x + threadIdx.x;
    if (i < N_NODES) {
        g_as[i] = g_dsp[0][i] + g_dsp[1][i];
        g_ad[i] = g_ddp[0][i] + g_ddp[1][i];
    }
}

// ================= fused softmax + aggregate (warp per dst) =================
__device__ __forceinline__ void agg_edge(int sj, float aj, int lane, float acc[8]) {
    const uint4* hs = (const uint4*)(g_featH + (size_t)sj * H);
    uint4 q = hs[lane];
    const __half2* h2 = (const __half2*)&q;
#pragma unroll
    for (int c = 0; c < 4; c++) {
        float2 f = __half22float2(h2[c]);
        acc[c * 2 + 0] += aj * f.x;
        acc[c * 2 + 1] += aj * f.y;
    }
}

__device__ __forceinline__ void agg_sweep(float a, int s, int cnt, int lane, float acc[8]) {
    int j = 0;
    for (; j + 2 <= cnt; j += 2) {
        float aj0 = __shfl_sync(0xFFFFFFFFu, a, j);
        int   sj0 = __shfl_sync(0xFFFFFFFFu, s, j);
        float aj1 = __shfl_sync(0xFFFFFFFFu, a, j + 1);
        int   sj1 = __shfl_sync(0xFFFFFFFFu, s, j + 1);
        uint4 q0 = ((const uint4*)(g_featH + (size_t)sj0 * H))[lane];
        uint4 q1 = ((const uint4*)(g_featH + (size_t)sj1 * H))[lane];
        const __half2* h0 = (const __half2*)&q0;
        const __half2* h1 = (const __half2*)&q1;
#pragma unroll
        for (int c = 0; c < 4; c++) {
            float2 f0 = __half22float2(h0[c]);
            float2 f1 = __half22float2(h1[c]);
            acc[c * 2 + 0] += aj0 * f0.x + aj1 * f1.x;
            acc[c * 2 + 1] += aj0 * f0.y + aj1 * f1.y;
        }
    }
    if (j < cnt) {
        float aj = __shfl_sync(0xFFFFFFFFu, a, j);
        int   sj = __shfl_sync(0xFFFFFFFFu, s, j);
        agg_edge(sj, aj, lane, acc);
    }
}

__device__ __forceinline__ void gat_attn_body(int warp, int lane, float acc[8]) {
    int beg = g_off[warp], end = g_off[warp + 1];
    int deg = end - beg;
    float ad = g_ad[warp];

    if (deg <= 32) {
        bool valid = lane < deg;
        int s = valid ? g_srcs[beg + lane] : 0;
        float e = -3.4e38f;
        if (valid) {
            e = g_as[s] + ad;
            e = (e > 0.f) ? e : NEG * e;
        }
        float m = e;
#pragma unroll
        for (int o = 16; o; o >>= 1) m = fmaxf(m, __shfl_xor_sync(0xFFFFFFFFu, m, o));
        float ex = valid ? expf(e - m) : 0.f;
        float denom = ex;
#pragma unroll
        for (int o = 16; o; o >>= 1) denom += __shfl_xor_sync(0xFFFFFFFFu, denom, o);
        float a = ex / fmaxf(denom, 1e-16f);
        agg_sweep(a, s, deg, lane, acc);
    } else {
        float m = -3.4e38f;
        for (int i = beg + lane; i < end; i += 32) {
            float e = g_as[g_srcs[i]] + ad;
            e = (e > 0.f) ? e : NEG * e;
            m = fmaxf(m, e);
        }
#pragma unroll
        for (int o = 16; o; o >>= 1) m = fmaxf(m, __shfl_xor_sync(0xFFFFFFFFu, m, o));
        float denom = 0.f;
        for (int i = beg + lane; i < end; i += 32) {
            float e = g_as[g_srcs[i]] + ad;
            e = (e > 0.f) ? e : NEG * e;
            float ex = expf(e - m);
            g_e[i] = ex;
            denom += ex;
        }
#pragma unroll
        for (int o = 16; o; o >>= 1) denom += __shfl_xor_sync(0xFFFFFFFFu, denom, o);
        float inv = 1.f / fmaxf(denom, 1e-16f);
        for (int i0 = beg; i0 < end; i0 += 32) {
            int i = i0 + lane;
            float a = 0.f; int s = 0;
            if (i < end) { s = g_srcs[i]; a = g_e[i] * inv; }
            agg_sweep(a, s, min(32, end - i0), lane, acc);
        }
    }
}

// layers 1-2: write fp16 featBH (next GEMM A)
__global__ void gat_attn(const float* __restrict__ bias) {
    int warp = (blockIdx.x * blockDim.x + threadIdx.x) >> 5;
    int lane = threadIdx.x & 31;
    if (warp >= N_NODES) return;
    float acc[8] = {};
    gat_attn_body(warp, lane, acc);
    const float* bp = bias + lane * 8;
    uint4 o;
    __half2 h0 = __floats2half2_rn(fmaxf(acc[0] + bp[0], 0.f), fmaxf(acc[1] + bp[1], 0.f));
    __half2 h1 = __floats2half2_rn(fmaxf(acc[2] + bp[2], 0.f), fmaxf(acc[3] + bp[3], 0.f));
    __half2 h2 = __floats2half2_rn(fmaxf(acc[4] + bp[4], 0.f), fmaxf(acc[5] + bp[5], 0.f));
    __half2 h3 = __floats2half2_rn(fmaxf(acc[6] + bp[6], 0.f), fmaxf(acc[7] + bp[7], 0.f));
    o.x = *(unsigned*)&h0; o.y = *(unsigned*)&h1;
    o.z = *(unsigned*)&h2; o.w = *(unsigned*)&h3;
    *(uint4*)(g_featBH + (size_t)warp * H + lane * 8) = o;
}

// layer 3: pool directly into g_hg
__global__ void gat_attn_pool(const float* __restrict__ bias, const int* __restrict__ batch) {
    int warp = (blockIdx.x * blockDim.x + threadIdx.x) >> 5;
    int lane = threadIdx.x & 31;
    if (warp >= N_NODES) return;
    float acc[8] = {};
    gat_attn_body(warp, lane, acc);
    int g = batch[warp];
    float* hg = g_hg + (size_t)g * H + lane * 8;
    const float* bp = bias + lane * 8;
#pragma unroll
    for (int c = 0; c < 8; c++)
        atomicAdd(&hg[c], fmaxf(acc[c] + bp[c], 0.f));
}

// ================= MLP head =================
__global__ void fc1_kernel(const float* __restrict__ w, const float* __restrict__ b) {
    __shared__ float sh[H];
    int g = blockIdx.x;
    float c = fmaxf(g_cnt[g], 1.f);
    sh[threadIdx.x] = g_hg[(size_t)g * H + threadIdx.x] / c;
    __syncthreads();
    int j = threadIdx.x;
    if (j < FC1) {
        float acc = b[j];
#pragma unroll 8
        for (int k = 0; k < H; k++)
            acc += sh[k] * w[(size_t)k * FC1 + j];
        g_fc1[(size_t)g * FC1 + j] = fmaxf(acc, 0.f);
    }
}

__global__ void fc2_kernel(const float* __restrict__ w, const float* __restrict__ b,
                           float* __restrict__ out) {
    int g = blockIdx.x;
    int o = threadIdx.x;
    if (o >= D_OUT) return;
    float acc = b[o];
#pragma unroll 4
    for (int k = 0; k < FC1; k++)
        acc += g_fc1[(size_t)g * FC1 + k] * w[(size_t)k * D_OUT + o];
    out[(size_t)g * D_OUT + o] = acc;
}

// ================= host =================
extern "C" void kernel_launch(void* const* d_in, const int* in_sizes, int n_in,
                              void* d_out, int out_size) {
    const float* x     = (const float*)d_in[0];
    const int*   ei    = (const int*)d_in[1];
    const int*   batch = (const int*)d_in[2];
    const float* W1 = (const float*)d_in[3];
    const float* a1s = (const float*)d_in[4];
    const float* a1d = (const float*)d_in[5];
    const float* b1 = (const float*)d_in[6];
    const float* W2 = (const float*)d_in[7];
    const float* a2s = (const float*)d_in[8];
    const float* a2d = (const float*)d_in[9];
    const float* b2 = (const float*)d_in[10];
    const float* W3 = (const float*)d_in[11];
    const float* a3s = (const float*)d_in[12];
    const float* a3d = (const float*)d_in[13];
    const float* b3 = (const float*)d_in[14];
    const float* fc1_w = (const float*)d_in[15];
    const float* fc1_b = (const float*)d_in[16];
    const float* fc2_w = (const float*)d_in[17];
    const float* fc2_b = (const float*)d_in[18];

    __half* x16 = nullptr;
    __half* featBH = nullptr;
    __half* W16 = nullptr;
    cudaGetSymbolAddress((void**)&x16, g_x16);
    cudaGetSymbolAddress((void**)&featBH, g_featBH);
    cudaGetSymbolAddress((void**)&W16, g_W16);

    static cudaStream_t s2 = nullptr;
    static cudaEvent_t evA = nullptr, evB = nullptr;
    if (!s2) {
        cudaStreamCreateWithFlags(&s2, cudaStreamNonBlocking);
        cudaEventCreateWithFlags(&evA, cudaEventDisableTiming);
        cudaEventCreateWithFlags(&evB, cudaEventDisableTiming);
    }

    dim3 gemmGrid(2, (N_NODES + 127) / 128);
    int edgeBlocks = (ET + 255) / 256;
    int nodeBlocksW = ((size_t)N_NODES * 32 + 255) / 256;
    int nodeBlocks = (N_NODES + 255) / 256;

    // ---- main: zero + counts, then conversions + layer-1 GEMM ----
    zero_deg<<<(G_GRAPHS * H + 255) / 256, 256>>>();                           // #1
    count_all<<<edgeBlocks, 256>>>(ei, batch);                                 // #2
    cudaEventRecord(evA, 0);

    conv_all<<<(CONV_TOT / 4 + 255) / 256, 256>>>(x, W1, W2, W3);              // #3
    sgemm_tc<<<gemmGrid, 256>>>(x16, W16, a1s, a1d, N_NODES, F_IN);            // #4 (profiled)

    // ---- side: CSR build, concurrent with conv + GEMM1 ----
    cudaStreamWaitEvent(s2, evA, 0);
    scan_local<<<NB_SCAN, 1024, 0, s2>>>();
    scan_bsums<<<1, 64, 0, s2>>>();
    scan_add<<<nodeBlocks, 256, 0, s2>>>();
    scatter_edges<<<edgeBlocks, 256, 0, s2>>>(ei);
    cudaEventRecord(evB, s2);

    combine_dots<<<nodeBlocks, 256>>>();
    cudaStreamWaitEvent(0, evB, 0);   // join before attention
    gat_attn<<<nodeBlocksW, 256>>>(b1);

    // ---- layer 2 ----
    sgemm_tc<<<gemmGrid, 256>>>(featBH, W16 + H * H, a2s, a2d, N_NODES, H);
    combine_dots<<<nodeBlocks, 256>>>();
    gat_attn<<<nodeBlocksW, 256>>>(b2);

    // ---- layer 3 (pool fused) ----
    sgemm_tc<<<gemmGrid, 256>>>(featBH, W16 + 2 * H * H, a3s, a3d, N_NODES, H);
    combine_dots<<<nodeBlocks, 256>>>();
    gat_attn_pool<<<nodeBlocksW, 256>>>(b3, batch);

    // ---- MLP head ----
    fc1_kernel<<<G_GRAPHS, H>>>(fc1_w, fc1_b);
    fc2_kernel<<<G_GRAPHS, 32>>>(fc2_w, fc2_b, (float*)d_out);
}

// round 13
// speedup vs baseline: 1.2476x; 1.0572x over previous
#include <cuda_runtime.h>
#include <cuda_fp16.h>
#include <math.h>

#define N_NODES 50000
#define N_EDGES 800000
#define ET (N_EDGES + N_NODES)   // edges + self loops = 850000
#define F_IN 128
#define H 256
#define G_GRAPHS 500
#define FC1 196
#define D_OUT 10
#define NEG 0.2f
#define NB_SCAN ((N_NODES + 1023) / 1024)   // 49 scan blocks

// ---------------- scratch (static device globals; no allocation) ----------------
__device__ __align__(16) __half g_featH[(size_t)N_NODES * H];   // h = A@W (fp16, GEMM out)
__device__ __align__(16) __half g_featBH[(size_t)N_NODES * H];  // attention out (fp16, next A)
__device__ __align__(16) __half g_x16[(size_t)N_NODES * F_IN];  // fp16 copy of x
__device__ __align__(16) __half g_W16[3][H * H];                // fp16 weights (W1 uses 128 rows)
__device__ float g_dsp[2][N_NODES];              // per-colblock dot partials (s)
__device__ float g_ddp[2][N_NODES];              // per-colblock dot partials (d)
__device__ float g_e[ET];                        // per-edge exp(e - m) (slow path)
__device__ int   g_deg[N_NODES];
__device__ int   g_off[N_NODES + 1];             // CSR row offsets (by dst)
__device__ int   g_pos[N_NODES];
__device__ int   g_srcs[ET];                     // CSR column indices (src node)
__device__ int   g_bsum[NB_SCAN];
__device__ int   g_bpre[NB_SCAN];
__device__ float g_hg[G_GRAPHS * H];             // pooled per-graph sums
__device__ float g_cnt[G_GRAPHS];
__device__ float g_fc1[G_GRAPHS * FC1];

// ================= CSR build =================
__global__ void zero_deg() {
    int i = blockIdx.x * blockDim.x + threadIdx.x;
    if (i < N_NODES) g_deg[i] = 0;
    if (i < G_GRAPHS * H) g_hg[i] = 0.f;
    if (i < G_GRAPHS) g_cnt[i] = 0.f;
}

__global__ void count_all(const int* __restrict__ ei, const int* __restrict__ batch) {
    int e = blockIdx.x * blockDim.x + threadIdx.x;
    if (e < ET) {
        int d = (e < N_EDGES) ? ei[N_EDGES + e] : (e - N_EDGES);
        atomicAdd(&g_deg[d], 1);
    }
    if (e < N_NODES) atomicAdd(&g_cnt[batch[e]], 1.f);
}

__global__ __launch_bounds__(1024) void scan_local() {
    __shared__ int ws[32];
    int tid = threadIdx.x, lane = tid & 31, wid = tid >> 5;
    int i = blockIdx.x * 1024 + tid;
    int v = (i < N_NODES) ? g_deg[i] : 0;
    int incl = v;
#pragma unroll
    for (int o = 1; o < 32; o <<= 1) {
        int t = __shfl_up_sync(0xFFFFFFFFu, incl, o);
        if (lane >= o) incl += t;
    }
    if (lane == 31) ws[wid] = incl;
    __syncthreads();
    if (wid == 0) {
        int w = ws[lane];
#pragma unroll
        for (int o = 1; o < 32; o <<= 1) {
            int t = __shfl_up_sync(0xFFFFFFFFu, w, o);
            if (lane >= o) w += t;
        }
        ws[lane] = w;
    }
    __syncthreads();
    int excl = (wid ? ws[wid - 1] : 0) + incl - v;
    if (i < N_NODES) g_off[i] = excl;
    if (tid == 0) g_bsum[blockIdx.x] = ws[31];
}

__global__ void scan_bsums() {
    __shared__ int sh[64];
    int tid = threadIdx.x;
    int v = (tid < NB_SCAN) ? g_bsum[tid] : 0;
    sh[tid] = v;
    __syncthreads();
#pragma unroll
    for (int o = 1; o < 64; o <<= 1) {
        int t = (tid >= o) ? sh[tid - o] : 0;
        __syncthreads();
        sh[tid] += t;
        __syncthreads();
    }
    if (tid < NB_SCAN) g_bpre[tid] = sh[tid] - v;
}

__global__ void scan_add() {
    int i = blockIdx.x * blockDim.x + threadIdx.x;
    if (i == 0) g_off[N_NODES] = ET;
    if (i < N_NODES) {
        int o = g_off[i] + g_bpre[i >> 10];
        g_off[i] = o;
        g_pos[i] = o;
    }
}

__global__ void scatter_edges(const int* __restrict__ ei) {
    int e = blockIdx.x * blockDim.x + threadIdx.x;
    if (e >= ET) return;
    int s, d;
    if (e < N_EDGES) { s = ei[e]; d = ei[N_EDGES + e]; }
    else             { s = d = e - N_EDGES; }
    int idx = atomicAdd(&g_pos[d], 1);
    g_srcs[idx] = s;
}

// ================= fp32 -> fp16 conversion of x and all weights =================
#define X_ELEMS (N_NODES * F_IN)          // 6,400,000
#define W1_ELEMS (F_IN * H)               // 32,768
#define W23_ELEMS (H * H)                 // 65,536
#define CONV_TOT (X_ELEMS + W1_ELEMS + 2 * W23_ELEMS)

__global__ void conv_all(const float* __restrict__ x, const float* __restrict__ W1,
                         const float* __restrict__ W2, const float* __restrict__ W3) {
    int i4 = blockIdx.x * blockDim.x + threadIdx.x;   // float4 index
    size_t off = (size_t)i4 * 4;
    if (off >= CONV_TOT) return;
    const float* src;
    __half* dst;
    if (off < X_ELEMS)                       { src = x + off;  dst = g_x16 + off; }
    else if (off < X_ELEMS + W1_ELEMS)       { size_t o = off - X_ELEMS;              src = W1 + o; dst = g_W16[0] + o; }
    else if (off < X_ELEMS + W1_ELEMS + W23_ELEMS) { size_t o = off - X_ELEMS - W1_ELEMS; src = W2 + o; dst = g_W16[1] + o; }
    else                                     { size_t o = off - X_ELEMS - W1_ELEMS - W23_ELEMS; src = W3 + o; dst = g_W16[2] + o; }
    float4 v = *(const float4*)src;
    __half2* d2 = (__half2*)dst;
    d2[0] = __floats2half2_rn(v.x, v.y);
    d2[1] = __floats2half2_rn(v.z, v.w);
}

// ================= pure-fp16 TC GEMM (3-stage cp.async, m16n8k16, ldmatrix) =================
// Dynamic SMEM: 3 stages of (A: 128x40 halves, B: 32x136 halves) + 2x128 floats
#define AS_STRIDE 40    // halves per A row (32 + 8 pad)
#define BS_STRIDE 136   // halves per B k-row (128 + 8 pad)
#define AS_HALVES (128 * AS_STRIDE)                 // 5120 halves / stage
#define BS_HALVES (32 * BS_STRIDE)                  // 4352 halves / stage
#define STAGE_HALVES (AS_HALVES + BS_HALVES)        // 9472
#define GEMM_SMEM_BYTES (3 * STAGE_HALVES * 2 + 2 * 128 * 4)   // 56832 + 1024 = 57856

__device__ __forceinline__ void cp16(unsigned dst, const void* src) {
    asm volatile("cp.async.cg.shared.global [%0], [%1], 16;" :: "r"(dst), "l"(src));
}

__global__ __launch_bounds__(256) void sgemm_tc(const __half* __restrict__ A,
                                                const __half* __restrict__ Wl,
                                                const float* __restrict__ avs,
                                                const float* __restrict__ avd,
                                                int M, int K) {
    extern __shared__ __half smem[];
    __half* As3 = smem;                              // 3 * AS_HALVES
    __half* Bs3 = smem + 3 * AS_HALVES;              // 3 * BS_HALVES
    float* sds = (float*)(smem + 3 * STAGE_HALVES);  // 128
    float* sdd = sds + 128;                          // 128

    int tid = threadIdx.x;
    int wid = tid >> 5, lane = tid & 31;
    int grp = lane >> 2, t4 = lane & 3;
    int wm = wid >> 2, wn = wid & 3;           // warp grid 2x4, warp tile 64x32
    int row0 = blockIdx.y * 128;
    int col0 = blockIdx.x * 128;

    int ac0 = tid * 2;                         // A chunk ids: row=c>>2, koff=(c&3)*8
    int bc0 = tid * 2;                         // B chunk ids: krow=c>>4, noff=(c&15)*8

    float acc[4][4][4] = {};
    int nit = K >> 5;

    if (tid < 128) { sds[tid] = 0.f; sdd[tid] = 0.f; }

    auto issue = [&](int it) {
        int k0 = it * 32;
        int buf = it % 3;
        unsigned a_base = (unsigned)__cvta_generic_to_shared(As3 + buf * AS_HALVES);
        unsigned b_base = (unsigned)__cvta_generic_to_shared(Bs3 + buf * BS_HALVES);
#pragma unroll
        for (int q = 0; q < 2; q++) {
            int c = ac0 + q;
            int row = c >> 2, koff = (c & 3) * 8;
            if (row0 + row < M)
                cp16(a_base + (row * AS_STRIDE + koff) * 2,
                     A + (size_t)(row0 + row) * K + k0 + koff);
            int cb = bc0 + q;
            int krow = cb >> 4, noff = (cb & 15) * 8;
            cp16(b_base + (krow * BS_STRIDE + noff) * 2,
                 Wl + (size_t)(k0 + krow) * 256 + col0 + noff);
        }
        asm volatile("cp.async.commit_group;");
    };

    auto comp = [&](int b) {
        unsigned a_base = (unsigned)__cvta_generic_to_shared(As3 + b * AS_HALVES);
        unsigned b_base = (unsigned)__cvta_generic_to_shared(Bs3 + b * BS_HALVES);
        int lr = lane & 15, lh = (lane >> 4) << 3;
#pragma unroll
        for (int ks = 0; ks < 32; ks += 16) {
            unsigned bf[2][4];
#pragma unroll
            for (int jj = 0; jj < 2; jj++) {
                unsigned addr = b_base + ((ks + lr) * BS_STRIDE + wn * 32 + jj * 16 + lh) * 2;
                asm volatile("ldmatrix.sync.aligned.m8n8.x4.trans.shared.b16 {%0,%1,%2,%3}, [%4];"
                             : "=r"(bf[jj][0]), "=r"(bf[jj][1]), "=r"(bf[jj][2]), "=r"(bf[jj][3])
                             : "r"(addr));
            }
#pragma unroll
            for (int i = 0; i < 4; i++) {
                unsigned af0, af1, af2, af3;
                unsigned addr = a_base + ((wm * 64 + i * 16 + lr) * AS_STRIDE + ks + lh) * 2;
                asm volatile("ldmatrix.sync.aligned.m8n8.x4.shared.b16 {%0,%1,%2,%3}, [%4];"
                             : "=r"(af0), "=r"(af1), "=r"(af2), "=r"(af3)
                             : "r"(addr));
#pragma unroll
                for (int jj = 0; jj < 2; jj++) {
#pragma unroll
                    for (int ns = 0; ns < 2; ns++) {
                        float* c = acc[i][jj * 2 + ns];
                        asm volatile("mma.sync.aligned.m16n8k16.row.col.f32.f16.f16.f32 "
                                     "{%0,%1,%2,%3}, {%4,%5,%6,%7}, {%8,%9}, {%0,%1,%2,%3};"
                                     : "+f"(c[0]), "+f"(c[1]), "+f"(c[2]), "+f"(c[3])
                                     : "r"(af0), "r"(af1), "r"(af2), "r"(af3),
                                       "r"(bf[jj][ns * 2]), "r"(bf[jj][ns * 2 + 1]));
                    }
                }
            }
        }
    };

    // ---- 3-stage pipelined mainloop: one __syncthreads per iteration ----
    issue(0);
    if (nit > 1) issue(1);
    for (int it = 0; it < nit; it++) {
        if (it + 1 < nit) asm volatile("cp.async.wait_group 1;");
        else              asm volatile("cp.async.wait_group 0;");
        __syncthreads();   // publishes stage it; retires all readers of comp(it-1)
        comp(it % 3);
        if (it + 2 < nit) issue(it + 2);   // buffer (it+2)%3 == (it-1)%3: all readers passed sync
    }

    // ---- attention-dot epilogue (fp32-exact from acc; shfl-reduce over t4 lanes) ----
    float a_s_r[8], a_d_r[8];
#pragma unroll
    for (int j = 0; j < 4; j++) {
        int col = col0 + wn * 32 + j * 8 + t4 * 2;
        a_s_r[j * 2 + 0] = avs[col];     a_s_r[j * 2 + 1] = avs[col + 1];
        a_d_r[j * 2 + 0] = avd[col];     a_d_r[j * 2 + 1] = avd[col + 1];
    }
    __syncthreads();
#pragma unroll
    for (int i = 0; i < 4; i++) {
        float ps0 = 0.f, pd0 = 0.f, ps1 = 0.f, pd1 = 0.f;
#pragma unroll
        for (int j = 0; j < 4; j++) {
            ps0 += acc[i][j][0] * a_s_r[j * 2] + acc[i][j][1] * a_s_r[j * 2 + 1];
            pd0 += acc[i][j][0] * a_d_r[j * 2] + acc[i][j][1] * a_d_r[j * 2 + 1];
            ps1 += acc[i][j][2] * a_s_r[j * 2] + acc[i][j][3] * a_s_r[j * 2 + 1];
            pd1 += acc[i][j][2] * a_d_r[j * 2] + acc[i][j][3] * a_d_r[j * 2 + 1];
        }
        ps0 += __shfl_xor_sync(0xFFFFFFFFu, ps0, 1); ps0 += __shfl_xor_sync(0xFFFFFFFFu, ps0, 2);
        pd0 += __shfl_xor_sync(0xFFFFFFFFu, pd0, 1); pd0 += __shfl_xor_sync(0xFFFFFFFFu, pd0, 2);
        ps1 += __shfl_xor_sync(0xFFFFFFFFu, ps1, 1); ps1 += __shfl_xor_sync(0xFFFFFFFFu, ps1, 2);
        pd1 += __shfl_xor_sync(0xFFFFFFFFu, pd1, 1); pd1 += __shfl_xor_sync(0xFFFFFFFFu, pd1, 2);
        if (t4 == 0) {
            int rl = wm * 64 + i * 16 + grp;
            atomicAdd(&sds[rl], ps0);     atomicAdd(&sdd[rl], pd0);
            atomicAdd(&sds[rl + 8], ps1); atomicAdd(&sdd[rl + 8], pd1);
        }
    }
    __syncthreads();
    if (tid < 128) {
        int row = row0 + tid;
        if (row < M) {
            g_dsp[blockIdx.x][row] = sds[tid];
            g_ddp[blockIdx.x][row] = sdd[tid];
        }
    }

    // ---- fp16 featH store ----
#pragma unroll
    for (int i = 0; i < 4; i++) {
#pragma unroll
        for (int j = 0; j < 4; j++) {
            int row = row0 + wm * 64 + i * 16 + grp;
            int col = col0 + wn * 32 + j * 8 + t4 * 2;
            if (row < M)
                *(__half2*)(g_featH + (size_t)row * 256 + col) =
                    __floats2half2_rn(acc[i][j][0], acc[i][j][1]);
            if (row + 8 < M)
                *(__half2*)(g_featH + (size_t)(row + 8) * 256 + col) =
                    __floats2half2_rn(acc[i][j][2], acc[i][j][3]);
        }
    }
}

// ================= fused softmax + aggregate (warp per dst) =================
__device__ __forceinline__ float node_as(int i) { return g_dsp[0][i] + g_dsp[1][i]; }
__device__ __forceinline__ float node_ad(int i) { return g_ddp[0][i] + g_ddp[1][i]; }

__device__ __forceinline__ void agg_edge(int sj, float aj, int lane, float acc[8]) {
    const uint4* hs = (const uint4*)(g_featH + (size_t)sj * H);
    uint4 q = hs[lane];
    const __half2* h2 = (const __half2*)&q;
#pragma unroll
    for (int c = 0; c < 4; c++) {
        float2 f = __half22float2(h2[c]);
        acc[c * 2 + 0] += aj * f.x;
        acc[c * 2 + 1] += aj * f.y;
    }
}

__device__ __forceinline__ void agg_sweep(float a, int s, int cnt, int lane, float acc[8]) {
    int j = 0;
    for (; j + 2 <= cnt; j += 2) {
        float aj0 = __shfl_sync(0xFFFFFFFFu, a, j);
        int   sj0 = __shfl_sync(0xFFFFFFFFu, s, j);
        float aj1 = __shfl_sync(0xFFFFFFFFu, a, j + 1);
        int   sj1 = __shfl_sync(0xFFFFFFFFu, s, j + 1);
        uint4 q0 = ((const uint4*)(g_featH + (size_t)sj0 * H))[lane];
        uint4 q1 = ((const uint4*)(g_featH + (size_t)sj1 * H))[lane];
        const __half2* h0 = (const __half2*)&q0;
        const __half2* h1 = (const __half2*)&q1;
#pragma unroll
        for (int c = 0; c < 4; c++) {
            float2 f0 = __half22float2(h0[c]);
            float2 f1 = __half22float2(h1[c]);
            acc[c * 2 + 0] += aj0 * f0.x + aj1 * f1.x;
            acc[c * 2 + 1] += aj0 * f0.y + aj1 * f1.y;
        }
    }
    if (j < cnt) {
        float aj = __shfl_sync(0xFFFFFFFFu, a, j);
        int   sj = __shfl_sync(0xFFFFFFFFu, s, j);
        agg_edge(sj, aj, lane, acc);
    }
}

__device__ __forceinline__ void gat_attn_body(int warp, int lane, float acc[8]) {
    int beg = g_off[warp], end = g_off[warp + 1];
    int deg = end - beg;
    float ad = node_ad(warp);

    if (deg <= 32) {
        bool valid = lane < deg;
        int s = valid ? g_srcs[beg + lane] : 0;
        float e = -3.4e38f;
        if (valid) {
            e = node_as(s) + ad;
            e = (e > 0.f) ? e : NEG * e;
        }
        float m = e;
#pragma unroll
        for (int o = 16; o; o >>= 1) m = fmaxf(m, __shfl_xor_sync(0xFFFFFFFFu, m, o));
        float ex = valid ? expf(e - m) : 0.f;
        float denom = ex;
#pragma unroll
        for (int o = 16; o; o >>= 1) denom += __shfl_xor_sync(0xFFFFFFFFu, denom, o);
        float a = ex / fmaxf(denom, 1e-16f);
        agg_sweep(a, s, deg, lane, acc);
    } else {
        float m = -3.4e38f;
        for (int i = beg + lane; i < end; i += 32) {
            float e = node_as(g_srcs[i]) + ad;
            e = (e > 0.f) ? e : NEG * e;
            m = fmaxf(m, e);
        }
#pragma unroll
        for (int o = 16; o; o >>= 1) m = fmaxf(m, __shfl_xor_sync(0xFFFFFFFFu, m, o));
        float denom = 0.f;
        for (int i = beg + lane; i < end; i += 32) {
            float e = node_as(g_srcs[i]) + ad;
            e = (e > 0.f) ? e : NEG * e;
            float ex = expf(e - m);
            g_e[i] = ex;
            denom += ex;
        }
#pragma unroll
        for (int o = 16; o; o >>= 1) denom += __shfl_xor_sync(0xFFFFFFFFu, denom, o);
        float inv = 1.f / fmaxf(denom, 1e-16f);
        for (int i0 = beg; i0 < end; i0 += 32) {
            int i = i0 + lane;
            float a = 0.f; int s = 0;
            if (i < end) { s = g_srcs[i]; a = g_e[i] * inv; }
            agg_sweep(a, s, min(32, end - i0), lane, acc);
        }
    }
}

// layers 1-2: write fp16 featBH (next GEMM A)
__global__ void gat_attn(const float* __restrict__ bias) {
    int warp = (blockIdx.x * blockDim.x + threadIdx.x) >> 5;
    int lane = threadIdx.x & 31;
    if (warp >= N_NODES) return;
    float acc[8] = {};
    gat_attn_body(warp, lane, acc);
    const float* bp = bias + lane * 8;
    uint4 o;
    __half2 h0 = __floats2half2_rn(fmaxf(acc[0] + bp[0], 0.f), fmaxf(acc[1] + bp[1], 0.f));
    __half2 h1 = __floats2half2_rn(fmaxf(acc[2] + bp[2], 0.f), fmaxf(acc[3] + bp[3], 0.f));
    __half2 h2 = __floats2half2_rn(fmaxf(acc[4] + bp[4], 0.f), fmaxf(acc[5] + bp[5], 0.f));
    __half2 h3 = __floats2half2_rn(fmaxf(acc[6] + bp[6], 0.f), fmaxf(acc[7] + bp[7], 0.f));
    o.x = *(unsigned*)&h0; o.y = *(unsigned*)&h1;
    o.z = *(unsigned*)&h2; o.w = *(unsigned*)&h3;
    *(uint4*)(g_featBH + (size_t)warp * H + lane * 8) = o;
}

// layer 3: pool directly into g_hg
__global__ void gat_attn_pool(const float* __restrict__ bias, const int* __restrict__ batch) {
    int warp = (blockIdx.x * blockDim.x + threadIdx.x) >> 5;
    int lane = threadIdx.x & 31;
    if (warp >= N_NODES) return;
    float acc[8] = {};
    gat_attn_body(warp, lane, acc);
    int g = batch[warp];
    float* hg = g_hg + (size_t)g * H + lane * 8;
    const float* bp = bias + lane * 8;
#pragma unroll
    for (int c = 0; c < 8; c++)
        atomicAdd(&hg[c], fmaxf(acc[c] + bp[c], 0.f));
}

// ================= MLP head =================
__global__ void fc1_kernel(const float* __restrict__ w, const float* __restrict__ b) {
    __shared__ float sh[H];
    int g = blockIdx.x;
    float c = fmaxf(g_cnt[g], 1.f);
    sh[threadIdx.x] = g_hg[(size_t)g * H + threadIdx.x] / c;
    __syncthreads();
    int j = threadIdx.x;
    if (j < FC1) {
        float acc = b[j];
#pragma unroll 8
        for (int k = 0; k < H; k++)
            acc += sh[k] * w[(size_t)k * FC1 + j];
        g_fc1[(size_t)g * FC1 + j] = fmaxf(acc, 0.f);
    }
}

__global__ void fc2_kernel(const float* __restrict__ w, const float* __restrict__ b,
                           float* __restrict__ out) {
    int g = blockIdx.x;
    int o = threadIdx.x;
    if (o >= D_OUT) return;
    float acc = b[o];
#pragma unroll 4
    for (int k = 0; k < FC1; k++)
        acc += g_fc1[(size_t)g * FC1 + k] * w[(size_t)k * D_OUT + o];
    out[(size_t)g * D_OUT + o] = acc;
}

// ================= host =================
extern "C" void kernel_launch(void* const* d_in, const int* in_sizes, int n_in,
                              void* d_out, int out_size) {
    const float* x     = (const float*)d_in[0];
    const int*   ei    = (const int*)d_in[1];
    const int*   batch = (const int*)d_in[2];
    const float* W1 = (const float*)d_in[3];
    const float* a1s = (const float*)d_in[4];
    const float* a1d = (const float*)d_in[5];
    const float* b1 = (const float*)d_in[6];
    const float* W2 = (const float*)d_in[7];
    const float* a2s = (const float*)d_in[8];
    const float* a2d = (const float*)d_in[9];
    const float* b2 = (const float*)d_in[10];
    const float* W3 = (const float*)d_in[11];
    const float* a3s = (const float*)d_in[12];
    const float* a3d = (const float*)d_in[13];
    const float* b3 = (const float*)d_in[14];
    const float* fc1_w = (const float*)d_in[15];
    const float* fc1_b = (const float*)d_in[16];
    const float* fc2_w = (const float*)d_in[17];
    const float* fc2_b = (const float*)d_in[18];

    __half* x16 = nullptr;
    __half* featBH = nullptr;
    __half* W16 = nullptr;
    cudaGetSymbolAddress((void**)&x16, g_x16);
    cudaGetSymbolAddress((void**)&featBH, g_featBH);
    cudaGetSymbolAddress((void**)&W16, g_W16);

    static cudaStream_t s2 = nullptr;
    static cudaEvent_t evA = nullptr, evB = nullptr;
    if (!s2) {
        cudaStreamCreateWithFlags(&s2, cudaStreamNonBlocking);
        cudaEventCreateWithFlags(&evA, cudaEventDisableTiming);
        cudaEventCreateWithFlags(&evB, cudaEventDisableTiming);
        cudaFuncSetAttribute(sgemm_tc, cudaFuncAttributeMaxDynamicSharedMemorySize,
                             GEMM_SMEM_BYTES);
    }

    dim3 gemmGrid(2, (N_NODES + 127) / 128);
    int edgeBlocks = (ET + 255) / 256;
    int nodeBlocksW = ((size_t)N_NODES * 32 + 255) / 256;
    int nodeBlocks = (N_NODES + 255) / 256;

    // ---- main: zero + counts, then conversions + layer-1 GEMM ----
    zero_deg<<<(G_GRAPHS * H + 255) / 256, 256>>>();                           // #1
    count_all<<<edgeBlocks, 256>>>(ei, batch);                                 // #2
    cudaEventRecord(evA, 0);

    conv_all<<<(CONV_TOT / 4 + 255) / 256, 256>>>(x, W1, W2, W3);              // #3
    sgemm_tc<<<gemmGrid, 256, GEMM_SMEM_BYTES>>>(x16, W16, a1s, a1d, N_NODES, F_IN);  // #4

    // ---- side: CSR build, concurrent with conv + GEMM1 ----
    cudaStreamWaitEvent(s2, evA, 0);
    scan_local<<<NB_SCAN, 1024, 0, s2>>>();
    scan_bsums<<<1, 64, 0, s2>>>();
    scan_add<<<nodeBlocks, 256, 0, s2>>>();
    scatter_edges<<<edgeBlocks, 256, 0, s2>>>(ei);
    cudaEventRecord(evB, s2);
    cudaStreamWaitEvent(0, evB, 0);   // join before attention

    // ---- layer 1 attention ----
    gat_attn<<<nodeBlocksW, 256>>>(b1);

    // ---- layer 2 ----
    sgemm_tc<<<gemmGrid, 256, GEMM_SMEM_BYTES>>>(featBH, W16 + H * H, a2s, a2d, N_NODES, H);
    gat_attn<<<nodeBlocksW, 256>>>(b2);

    // ---- layer 3 (pool fused) ----
    sgemm_tc<<<gemmGrid, 256, GEMM_SMEM_BYTES>>>(featBH, W16 + 2 * H * H, a3s, a3d, N_NODES, H);
    gat_attn_pool<<<nodeBlocksW, 256>>>(b3, batch);

    // ---- MLP head ----
    fc1_kernel<<<G_GRAPHS, H>>>(fc1_w, fc1_b);
    fc2_kernel<<<G_GRAPHS, 32>>>(fc2_w, fc2_b, (float*)d_out);
}